// round 2
// baseline (speedup 1.0000x reference)
#include <cuda_runtime.h>
#include <math.h>

#define N_ 32
#define C_ 512
#define P_ 1024
#define K_ 64
#define ALPHAF 100.0f
#define EPSF 1e-12f

typedef unsigned long long u64;

__device__ __forceinline__ u64 pack2(float lo, float hi) {
    u64 r;
    asm("mov.b64 %0, {%1, %2};" : "=l"(r) : "f"(lo), "f"(hi));
    return r;
}
__device__ __forceinline__ void unpack2(u64 v, float& lo, float& hi) {
    asm("mov.b64 {%0, %1}, %2;" : "=f"(lo), "=f"(hi) : "l"(v));
}
__device__ __forceinline__ void fma2(u64& d, u64 a, u64 b) {
    asm("fma.rn.f32x2 %0, %1, %2, %0;" : "+l"(d) : "l"(a), "l"(b));
}

// Scratch (device globals; no allocations allowed)
__device__ float g_invn[N_ * P_];
__device__ float g_bias[K_];
__device__ float g_assign[(size_t)N_ * P_ * K_];  // [n][p][k]
__device__ float g_asum[N_ * K_];
__device__ float g_nss[N_];

// ---------------------------------------------------------------------------
// K0: inv-norm per (n,p), float4 over p. grid 32 x 256 threads = 8192 threads
// each owning 4 p-columns. Block 0 also computes bias; 1,2 zero scratch.
// ---------------------------------------------------------------------------
__global__ __launch_bounds__(256) void k0_prep(const float* __restrict__ x,
                                               const float* __restrict__ vocabs) {
    int g4 = blockIdx.x * 256 + threadIdx.x;   // 8192 = N*P/4
    int n = g4 >> 8;                           // 256 float4 per n
    int p4 = g4 & 255;
    const float4* xp = (const float4*)(x + (size_t)n * C_ * P_) + p4;
    float4 ss = make_float4(0.f, 0.f, 0.f, 0.f);
#pragma unroll 8
    for (int c = 0; c < C_; c++) {
        float4 v = xp[(size_t)c * (P_ / 4)];
        ss.x = fmaf(v.x, v.x, ss.x);
        ss.y = fmaf(v.y, v.y, ss.y);
        ss.z = fmaf(v.z, v.z, ss.z);
        ss.w = fmaf(v.w, v.w, ss.w);
    }
    float4 o;
    o.x = 1.0f / fmaxf(sqrtf(ss.x), EPSF);
    o.y = 1.0f / fmaxf(sqrtf(ss.y), EPSF);
    o.z = 1.0f / fmaxf(sqrtf(ss.z), EPSF);
    o.w = 1.0f / fmaxf(sqrtf(ss.w), EPSF);
    ((float4*)g_invn)[g4] = o;

    if (blockIdx.x == 0) {
        int lane = threadIdx.x & 31;
        int w = threadIdx.x >> 5;
#pragma unroll
        for (int r = 0; r < 8; r++) {
            int k = w * 8 + r;
            float s = 0.0f;
#pragma unroll
            for (int j = 0; j < 16; j++) {
                float v = vocabs[k * C_ + lane + 32 * j];
                s = fmaf(v, v, s);
            }
#pragma unroll
            for (int o2 = 16; o2; o2 >>= 1) s += __shfl_xor_sync(0xffffffffu, s, o2);
            if (lane == 0) g_bias[k] = -ALPHAF * sqrtf(s);
        }
    } else if (blockIdx.x == 1) {
#pragma unroll
        for (int i = 0; i < 8; i++) g_asum[threadIdx.x + 256 * i] = 0.0f;
    } else if (blockIdx.x == 2) {
        if (threadIdx.x < N_) g_nss[threadIdx.x] = 0.0f;
    }
}

// ---------------------------------------------------------------------------
// K1: logits GEMM (K=64 x Ptile=64 over C) + bias + softmax over K.
// grid (16, 32). 256 threads: thread (tx,ty) owns 8k x 2p; acc packed over k.
// ---------------------------------------------------------------------------
#define WS_STRIDE 68
#define LS_STRIDE 65

__global__ __launch_bounds__(256) void k1_assign(const float* __restrict__ x,
                                                 const float* __restrict__ vocabs) {
    __shared__ float sm[32 * WS_STRIDE + 32 * 64];
    float* ws = sm;                    // [32][WS_STRIDE]  w^T: [c][k]
    float* xs = sm + 32 * WS_STRIDE;   // [32][64]         [c][p]

    int t = threadIdx.x;
    int tx = t & 31, ty = t >> 5;
    int n = blockIdx.y;
    int p0 = blockIdx.x * 64;
    int k0 = ty * 8;
    int pl = tx * 2;

    u64 accp[4][2];
#pragma unroll
    for (int i = 0; i < 4; i++) { accp[i][0] = 0ULL; accp[i][1] = 0ULL; }

    const float* xb = x + (size_t)n * C_ * P_ + p0;

    for (int c0 = 0; c0 < C_; c0 += 32) {
#pragma unroll
        for (int i = 0; i < 8; i++) {
            int e = t + 256 * i;
            int k = e >> 5, c = e & 31;
            ws[c * WS_STRIDE + k] = (2.0f * ALPHAF) * vocabs[k * C_ + c0 + c];
        }
#pragma unroll
        for (int i = 0; i < 8; i++) {
            int e = t + 256 * i;
            int c = e >> 6, p = e & 63;
            xs[c * 64 + p] = xb[(size_t)(c0 + c) * P_ + p];
        }
        __syncthreads();
#pragma unroll
        for (int cc = 0; cc < 32; cc++) {
            ulonglong2 w01 = *(const ulonglong2*)(ws + cc * WS_STRIDE + k0);
            ulonglong2 w23 = *(const ulonglong2*)(ws + cc * WS_STRIDE + k0 + 4);
            float2 b = *(const float2*)(xs + cc * 64 + pl);
            u64 bx = pack2(b.x, b.x);
            u64 by = pack2(b.y, b.y);
            fma2(accp[0][0], w01.x, bx); fma2(accp[0][1], w01.x, by);
            fma2(accp[1][0], w01.y, bx); fma2(accp[1][1], w01.y, by);
            fma2(accp[2][0], w23.x, bx); fma2(accp[2][1], w23.x, by);
            fma2(accp[3][0], w23.y, bx); fma2(accp[3][1], w23.y, by);
        }
        __syncthreads();
    }

    // unpack
    float acc[8][2];
#pragma unroll
    for (int i = 0; i < 4; i++) {
        unpack2(accp[i][0], acc[2 * i][0], acc[2 * i + 1][0]);
        unpack2(accp[i][1], acc[2 * i][1], acc[2 * i + 1][1]);
    }

    float inv0 = g_invn[n * P_ + p0 + pl];
    float inv1 = g_invn[n * P_ + p0 + pl + 1];
    float* ls = sm;  // [64][LS_STRIDE]
#pragma unroll
    for (int i = 0; i < 8; i++) {
        float b = g_bias[k0 + i];
        ls[(pl + 0) * LS_STRIDE + k0 + i] = fmaf(acc[i][0], inv0, b);
        ls[(pl + 1) * LS_STRIDE + k0 + i] = fmaf(acc[i][1], inv1, b);
    }
    __syncthreads();

    if (t < 64) {
        float m = -1e30f;
#pragma unroll
        for (int k = 0; k < 64; k++) m = fmaxf(m, ls[t * LS_STRIDE + k]);
        float s = 0.0f;
#pragma unroll
        for (int k = 0; k < 64; k++) {
            float e = __expf(ls[t * LS_STRIDE + k] - m);
            ls[t * LS_STRIDE + k] = e;
            s += e;
        }
        float r = 1.0f / s;
        float* gp = g_assign + ((size_t)n * P_ + p0 + t) * K_;
#pragma unroll
        for (int k = 0; k < 64; k += 4) {
            float4 o;
            o.x = ls[t * LS_STRIDE + k + 0] * r;
            o.y = ls[t * LS_STRIDE + k + 1] * r;
            o.z = ls[t * LS_STRIDE + k + 2] * r;
            o.w = ls[t * LS_STRIDE + k + 3] * r;
            ls[t * LS_STRIDE + k + 0] = o.x;
            ls[t * LS_STRIDE + k + 1] = o.y;
            ls[t * LS_STRIDE + k + 2] = o.z;
            ls[t * LS_STRIDE + k + 3] = o.w;
            *(float4*)(gp + k) = o;
        }
    }
    __syncthreads();

    if (t < 64) {
        float s = 0.0f;
#pragma unroll
        for (int r2 = 0; r2 < 64; r2++) s += ls[r2 * LS_STRIDE + t];
        atomicAdd(&g_asum[n * K_ + t], s);
    }
}

// ---------------------------------------------------------------------------
// K2: vlad GEMM  out[n,k,c] = sum_p (a*invn)[p][k] * x[c][p] - asum[k]*vocab[k][c]
// grid (8, 32). thread owns 8k x 2c; acc packed over k.
// ---------------------------------------------------------------------------
#define XS2_STRIDE 66

__global__ __launch_bounds__(256) void k2_vlad(const float* __restrict__ x,
                                               const float* __restrict__ vocabs,
                                               float* __restrict__ out) {
    __shared__ float as_[32 * 64];          // [p][k]
    __shared__ float xs[32 * XS2_STRIDE];   // [p][c]

    int t = threadIdx.x;
    int tx = t & 31, ty = t >> 5;
    int n = blockIdx.y;
    int c0 = blockIdx.x * 64;
    int k0 = ty * 8;
    int cl = tx * 2;

    u64 accp[4][2];
#pragma unroll
    for (int i = 0; i < 4; i++) { accp[i][0] = 0ULL; accp[i][1] = 0ULL; }

    const float* xb = x + (size_t)n * C_ * P_;
    const float* ab = g_assign + (size_t)n * P_ * K_;
    const float* ib = g_invn + n * P_;

    for (int p0 = 0; p0 < P_; p0 += 32) {
        const float4* a4 = (const float4*)(ab + (size_t)p0 * K_);
#pragma unroll
        for (int i = 0; i < 2; i++) {
            int e4 = t + 256 * i;
            int p = e4 >> 4;
            float4 v = a4[e4];
            float inv = ib[p0 + p];
            v.x *= inv; v.y *= inv; v.z *= inv; v.w *= inv;
            *(float4*)(as_ + e4 * 4) = v;
        }
#pragma unroll
        for (int i = 0; i < 8; i++) {
            int e = t + 256 * i;
            int c = e >> 5, p = e & 31;
            xs[p * XS2_STRIDE + c] = xb[(size_t)(c0 + c) * P_ + p0 + p];
        }
        __syncthreads();
#pragma unroll
        for (int pp = 0; pp < 32; pp++) {
            ulonglong2 a01 = *(const ulonglong2*)(as_ + pp * 64 + k0);
            ulonglong2 a23 = *(const ulonglong2*)(as_ + pp * 64 + k0 + 4);
            float2 b = *(const float2*)(xs + pp * XS2_STRIDE + cl);
            u64 bx = pack2(b.x, b.x);
            u64 by = pack2(b.y, b.y);
            fma2(accp[0][0], a01.x, bx); fma2(accp[0][1], a01.x, by);
            fma2(accp[1][0], a01.y, bx); fma2(accp[1][1], a01.y, by);
            fma2(accp[2][0], a23.x, bx); fma2(accp[2][1], a23.x, by);
            fma2(accp[3][0], a23.y, bx); fma2(accp[3][1], a23.y, by);
        }
        __syncthreads();
    }

    float acc[8][2];
#pragma unroll
    for (int i = 0; i < 4; i++) {
        unpack2(accp[i][0], acc[2 * i][0], acc[2 * i + 1][0]);
        unpack2(accp[i][1], acc[2 * i][1], acc[2 * i + 1][1]);
    }

#pragma unroll
    for (int i = 0; i < 8; i++) {
        int k = k0 + i;
        float s = g_asum[n * K_ + k];
        float v0 = vocabs[k * C_ + c0 + cl];
        float v1 = vocabs[k * C_ + c0 + cl + 1];
        float2 o;
        o.x = fmaf(-s, v0, acc[i][0]);
        o.y = fmaf(-s, v1, acc[i][1]);
        *(float2*)(out + (size_t)n * (K_ * C_) + (size_t)k * C_ + c0 + cl) = o;
    }
}

// ---------------------------------------------------------------------------
// K3a: intra-normalize each [n,k,:] row, accumulate per-n sumsq.
// ---------------------------------------------------------------------------
__global__ __launch_bounds__(256) void k3a_intra(float* __restrict__ out) {
    int n = blockIdx.y, k = blockIdx.x, t = threadIdx.x;
    float* row = out + (size_t)n * (K_ * C_) + (size_t)k * C_;
    float2 v = *(float2*)(row + t * 2);
    float ss = v.x * v.x + v.y * v.y;
#pragma unroll
    for (int o = 16; o; o >>= 1) ss += __shfl_xor_sync(0xffffffffu, ss, o);
    __shared__ float wsum[8];
    if ((t & 31) == 0) wsum[t >> 5] = ss;
    __syncthreads();
    float tot = wsum[0] + wsum[1] + wsum[2] + wsum[3] +
                wsum[4] + wsum[5] + wsum[6] + wsum[7];
    float rinv = 1.0f / fmaxf(sqrtf(tot), EPSF);
    v.x *= rinv; v.y *= rinv;
    *(float2*)(row + t * 2) = v;
    if (t == 0) atomicAdd(&g_nss[n], tot * rinv * rinv);
}

// ---------------------------------------------------------------------------
// K3b: final global normalization per n (in place).
// ---------------------------------------------------------------------------
__global__ __launch_bounds__(256) void k3b_final(float* __restrict__ out) {
    int g4 = blockIdx.x * 256 + threadIdx.x;
    int n = (g4 * 4) >> 15;
    float r = 1.0f / fmaxf(sqrtf(g_nss[n]), EPSF);
    float4 v = ((float4*)out)[g4];
    v.x *= r; v.y *= r; v.z *= r; v.w *= r;
    ((float4*)out)[g4] = v;
}

// ---------------------------------------------------------------------------
extern "C" void kernel_launch(void* const* d_in, const int* in_sizes, int n_in,
                              void* d_out, int out_size) {
    const float* x = (const float*)d_in[0];
    const float* vocabs = (const float*)d_in[1];
    if (n_in >= 2 && in_sizes[0] == K_ * C_ && in_sizes[1] == N_ * C_ * P_) {
        vocabs = (const float*)d_in[0];
        x = (const float*)d_in[1];
    }
    float* out = (float*)d_out;

    k0_prep<<<32, 256>>>(x, vocabs);
    k1_assign<<<dim3(16, 32), 256>>>(x, vocabs);
    k2_vlad<<<dim3(8, 32), 256>>>(x, vocabs, out);
    k3a_intra<<<dim3(64, 32), 256>>>(out);
    k3b_final<<<1024, 256>>>(out);
}